// round 7
// baseline (speedup 1.0000x reference)
#include <cuda_runtime.h>
#include <cuda_bf16.h>
#include <cstdint>

typedef unsigned long long ull;

#define NPTS 16384
#define KCH  128
#define CG_TOTAL 3436
#define NW 20                      // 12 mixer + 8 iter weight matrices

// ---- scratch (device globals; no runtime allocation allowed) ----
__device__ float g_m1[(size_t)NPTS * 16 * KCH];   // mixed[1]
__device__ float g_m2[(size_t)NPTS * 16 * KCH];   // mixed[2]
__device__ float g_tp[(size_t)NPTS * 16 * KCH];   // tensor-product result
__device__ alignas(16) ull g_cgdup[CG_TOTAL];     // compacted cg, duplicated (c,c)
__device__ __nv_bfloat16 g_wthi[(size_t)NW * 128 * 128];  // W^T hi split, [w][q][k]
__device__ __nv_bfloat16 g_wtlo[(size_t)NW * 128 * 128];  // W^T lo split

// ---- packed f32x2 helpers ----
__device__ __forceinline__ ull dup2(float x) {
    ull r; asm("mov.b64 %0, {%1, %1};" : "=l"(r) : "f"(x)); return r;
}
__device__ __forceinline__ void ffma2(ull& d, ull a, ull b) {
    asm("fma.rn.f32x2 %0, %1, %2, %0;" : "+l"(d) : "l"(a), "l"(b));
}
__device__ __forceinline__ ull fmul2(ull a, ull b) {
    ull d; asm("mul.rn.f32x2 %0, %1, %2;" : "=l"(d) : "l"(a), "l"(b)); return d;
}

// ---- sm_80-compatible tensor-core primitives ----
__device__ __forceinline__ uint32_t smem_u32(const void* p) {
    uint32_t a;
    asm("{ .reg .u64 t; cvta.to.shared.u64 t, %1; cvt.u32.u64 %0, t; }" : "=r"(a) : "l"(p));
    return a;
}
__device__ __forceinline__ void ldsm4(uint32_t* r, uint32_t a) {
    asm volatile("ldmatrix.sync.aligned.m8n8.x4.shared.b16 {%0,%1,%2,%3}, [%4];"
        : "=r"(r[0]), "=r"(r[1]), "=r"(r[2]), "=r"(r[3]) : "r"(a));
}
__device__ __forceinline__ void ldsm2(uint32_t* r, uint32_t a) {
    asm volatile("ldmatrix.sync.aligned.m8n8.x2.shared.b16 {%0,%1}, [%2];"
        : "=r"(r[0]), "=r"(r[1]) : "r"(a));
}
__device__ __forceinline__ void mma_bf16(float* c, const uint32_t* a, const uint32_t* b) {
    asm volatile("mma.sync.aligned.m16n8k16.row.col.f32.bf16.bf16.f32 "
        "{%0,%1,%2,%3}, {%4,%5,%6,%7}, {%8,%9}, {%0,%1,%2,%3};"
        : "+f"(c[0]), "+f"(c[1]), "+f"(c[2]), "+f"(c[3])
        : "r"(a[0]), "r"(a[1]), "r"(a[2]), "r"(a[3]), "r"(b[0]), "r"(b[1]));
}

// bf16 split: v = hi + lo  (hi = rn(v), lo = rn(v - hi))
__device__ __forceinline__ void split_bf16(float v, unsigned short& h, unsigned short& l) {
    __nv_bfloat16 hb = __float2bfloat16(v);
    float r = v - __bfloat162float(hb);
    __nv_bfloat16 lb = __float2bfloat16(r);
    h = __bfloat16_as_ushort(hb);
    l = __bfloat16_as_ushort(lb);
}
__device__ __forceinline__ uint32_t pack16(unsigned short a, unsigned short b) {
    return (uint32_t)a | ((uint32_t)b << 16);
}

// ============================================================================
// prep: compact cg into path order (l2 -> l1 -> i -> j -> l -> m), dup (c,c)
// ============================================================================
__global__ void prep_cg_kernel(const float* __restrict__ cg) {
    int idx = blockIdx.x * blockDim.x + threadIdx.x;
    if (idx >= CG_TOTAL) return;
    int off = 0;
    for (int l2 = 0; l2 < 4; l2++) {
        int d2 = 2 * l2 + 1;
        for (int l1 = 0; l1 < 4; l1++) {
            int d1 = 2 * l1 + 1;
            for (int i = 0; i < d1; i++)
                for (int j = 0; j < d2; j++)
                    for (int l = 0; l < 4; l++) {
                        int lo = (l1 > l2) ? (l1 - l2) : (l2 - l1);
                        if (l < lo || l > l1 + l2) continue;
                        int dl = 2 * l + 1;
                        for (int m = 0; m < dl; m++) {
                            if (off == idx) {
                                float c = cg[((((l1 * 4 + l2) * 4 + l) * 7 + i) * 7 + j) * 7 + m];
                                g_cgdup[idx] = dup2(c);
                                return;
                            }
                            off++;
                        }
                    }
        }
    }
}

// ============================================================================
// prep: transpose + bf16-split all 20 weight matrices once.
// ============================================================================
__global__ void prep_w_kernel(const float* __restrict__ mixer, const float* __restrict__ iterw) {
    int b = blockIdx.x;
    const float* W = (b < 12) ? (mixer + (size_t)b * 16384) : (iterw + (size_t)(b - 12) * 16384);
    __nv_bfloat16* hi = g_wthi + (size_t)b * 16384;
    __nv_bfloat16* lo = g_wtlo + (size_t)b * 16384;
    for (int idx = threadIdx.x; idx < 16384; idx += 256) {
        int q = idx & 127, k = idx >> 7;
        float v = W[idx];
        unsigned short h, l;
        split_bf16(v, h, l);
        hi[q * 128 + k] = __ushort_as_bfloat16(h);
        lo[q * 128 + k] = __ushort_as_bfloat16(l);
    }
}

// ============================================================================
// Fused stage GEMM (HMMA): unchanged from R6 (passing, 2 CTAs/SM).
// ============================================================================
#define RS 272                       // padded row stride (bytes), 256 data + 16
#define A_T (64 * RS)                // 17408
#define A_HI 0
#define A_LO A_T
#define W_HI (2 * A_T)
#define W_LO (2 * A_T + 128 * RS)
#define GEMM_SMEM (2 * A_T + 2 * 128 * RS)   // 104448 B

__global__ __launch_bounds__(256, 2) void tc_gemm_stage(
    const float* __restrict__ s0, const float* __restrict__ s1,
    const float* __restrict__ s2, const float* __restrict__ s3,
    float* __restrict__ d0, float* __restrict__ d1, float* __restrict__ d2,
    const __nv_bfloat16* __restrict__ whiB, const __nv_bfloat16* __restrict__ wloB,
    int wbase, int accum)
{
    extern __shared__ char smem[];
    const int tid = threadIdx.x;
    const int wid = tid >> 5;
    const int lane = tid & 31;

    const int bid = blockIdx.x;
    const int stage = bid >> 12;
    const int t = bid & 4095;
    int l, tcum;
    if (t >= 2304)      { l = 3; tcum = 2304; }
    else if (t >= 1024) { l = 2; tcum = 1024; }
    else if (t >= 256)  { l = 1; tcum = 256; }
    else                { l = 0; tcum = 0; }
    const int tileInL = t - tcum;

    const float* srcL = (l == 0) ? s0 : (l == 1) ? s1 : (l == 2) ? s2 : s3;
    float* dstS = (stage == 0) ? d0 : (stage == 1) ? d1 : d2;
    const size_t OFFL[4] = {0, (size_t)1 * NPTS * KCH, (size_t)4 * NPTS * KCH, (size_t)9 * NPTS * KCH};
    const float* A = srcL + (size_t)tileInL * 64 * 128;
    float* C = dstS + OFFL[l] + (size_t)tileInL * 64 * 128;
    const int w = wbase + stage * 4 + l;
    const __nv_bfloat16* wthi = whiB + (size_t)w * 16384;
    const __nv_bfloat16* wtlo = wloB + (size_t)w * 16384;

    for (int u = tid; u < 2048; u += 256) {
        int r = u >> 4, c = u & 15;
        *(uint4*)(smem + W_HI + r * RS + c * 16) = *(const uint4*)((const char*)wthi + r * 256 + c * 16);
        *(uint4*)(smem + W_LO + r * RS + c * 16) = *(const uint4*)((const char*)wtlo + r * 256 + c * 16);
    }

#pragma unroll
    for (int it = 0; it < 8; it++) {
        int idx = tid + (it << 8);
        int row = idx >> 5;
        int kq = (idx & 31) << 2;
        float4 v = *(const float4*)(A + (size_t)row * 128 + kq);
        unsigned short h0, l0, h1, l1, h2, l2, h3, l3;
        split_bf16(v.x, h0, l0); split_bf16(v.y, h1, l1);
        split_bf16(v.z, h2, l2); split_bf16(v.w, h3, l3);
        ull hv = (ull)pack16(h0, h1) | ((ull)pack16(h2, h3) << 32);
        ull lv = (ull)pack16(l0, l1) | ((ull)pack16(l2, l3) << 32);
        *(ull*)(smem + A_HI + row * RS + kq * 2) = hv;
        *(ull*)(smem + A_LO + row * RS + kq * 2) = lv;
    }
    __syncthreads();

    const uint32_t sb = smem_u32(smem);
    const int warpM = (wid >> 2) << 5;
    const int warpN = (wid & 3) << 5;

    float acc[2][4][4];
#pragma unroll
    for (int mt = 0; mt < 2; mt++)
#pragma unroll
        for (int nt = 0; nt < 4; nt++)
#pragma unroll
            for (int i = 0; i < 4; i++) acc[mt][nt][i] = 0.0f;

    const int aRow = lane & 15;
    const uint32_t aK = (lane & 16) ? 16 : 0;
    const int bRow = lane & 7;
    const uint32_t bK = (lane & 8) ? 16 : 0;

#pragma unroll
    for (int kc = 0; kc < 8; kc++) {
        const uint32_t kb = kc * 32;
        uint32_t a_hi[2][4], a_lo[2][4];
#pragma unroll
        for (int mt = 0; mt < 2; mt++) {
            uint32_t off = (uint32_t)((warpM + mt * 16 + aRow) * RS) + kb + aK;
            ldsm4(a_hi[mt], sb + A_HI + off);
            ldsm4(a_lo[mt], sb + A_LO + off);
        }
#pragma unroll
        for (int nt = 0; nt < 4; nt++) {
            uint32_t off = (uint32_t)((warpN + nt * 8 + bRow) * RS) + kb + bK;
            uint32_t bh[2], bl[2];
            ldsm2(bh, sb + W_HI + off);
            ldsm2(bl, sb + W_LO + off);
#pragma unroll
            for (int mt = 0; mt < 2; mt++) {
                mma_bf16(acc[mt][nt], a_hi[mt], bh);
                mma_bf16(acc[mt][nt], a_hi[mt], bl);
                mma_bf16(acc[mt][nt], a_lo[mt], bh);
            }
        }
    }

    const int mrow = lane >> 2;
    const int ncol = (lane & 3) << 1;
#pragma unroll
    for (int mt = 0; mt < 2; mt++) {
#pragma unroll
        for (int nt = 0; nt < 4; nt++) {
            int row0 = warpM + mt * 16 + mrow;
            int col = warpN + nt * 8 + ncol;
            float2* p0 = (float2*)(C + (size_t)row0 * 128 + col);
            float2* p1 = (float2*)(C + (size_t)(row0 + 8) * 128 + col);
            float2 v0 = make_float2(acc[mt][nt][0], acc[mt][nt][1]);
            float2 v1 = make_float2(acc[mt][nt][2], acc[mt][nt][3]);
            if (accum) {
                float2 c0 = *p0, c1 = *p1;
                v0.x += c0.x; v0.y += c0.y;
                v1.x += c1.x; v1.y += c1.y;
            }
            *p0 = v0;
            *p1 = v1;
        }
    }
}

// ============================================================================
// Tensor product v2: 2 CTAs/SM (regs<=128), paired LDS.128 cg loads.
// acc resident (64 regs); b per-l2 (<=14), a per-(l2,l1) reloaded (L1 hits).
// Coefficient walk order unchanged: l2 -> l1 -> i -> j -> l -> m.
// ============================================================================
__global__ __launch_bounds__(256, 2) void tp_kernel(
    const float* __restrict__ aBase, const float* __restrict__ bBase,
    float* __restrict__ oBase)
{
    __shared__ alignas(16) ull s_cg[CG_TOTAL];
    for (int i = threadIdx.x; i < CG_TOTAL / 2; i += 256)
        ((ulonglong2*)s_cg)[i] = ((const ulonglong2*)g_cgdup)[i];
    __syncthreads();

    const int gid = blockIdx.x * 256 + threadIdx.x;
    const int kq = (gid & 31) << 2;       // channel offset (floats)
    const int n  = gid >> 5;

    constexpr int CUM[4] = {0, 1, 4, 9};
    constexpr int OFFL[4] = {0, 1 * NPTS * KCH, 4 * NPTS * KCH, 9 * NPTS * KCH};

    ull acc[16][2];
#pragma unroll
    for (int r = 0; r < 16; r++) { acc[r][0] = 0ull; acc[r][1] = 0ull; }

    int cgi = 0;          // compile-time after full unroll
    ull codd = 0;         // carried odd element of the current LDS.128 pair

#pragma unroll
    for (int l2 = 0; l2 < 4; l2++) {
        const int d2 = 2 * l2 + 1;
        ull b[7][2];
#pragma unroll
        for (int j = 0; j < d2; j++) {
            ulonglong2 v = *(const ulonglong2*)(bBase + OFFL[l2] + (n * d2 + j) * KCH + kq);
            b[j][0] = v.x; b[j][1] = v.y;
        }
#pragma unroll
        for (int l1 = 0; l1 < 4; l1++) {
            const int d1 = 2 * l1 + 1;
            ull a[7][2];
#pragma unroll
            for (int i = 0; i < d1; i++) {
                ulonglong2 v = *(const ulonglong2*)(aBase + OFFL[l1] + (n * d1 + i) * KCH + kq);
                a[i][0] = v.x; a[i][1] = v.y;
            }
#pragma unroll
            for (int i = 0; i < d1; i++) {
#pragma unroll
                for (int j = 0; j < d2; j++) {
                    ull p0 = fmul2(a[i][0], b[j][0]);
                    ull p1 = fmul2(a[i][1], b[j][1]);
#pragma unroll
                    for (int l = 0; l < 4; l++) {
                        const int lo = (l1 > l2) ? (l1 - l2) : (l2 - l1);
                        if (l < lo || l > l1 + l2) continue;
                        const int dl = 2 * l + 1;
#pragma unroll
                        for (int m = 0; m < dl; m++) {
                            ull c;
                            if ((cgi & 1) == 0) {          // constant-folded branch
                                ulonglong2 t = *(const ulonglong2*)&s_cg[cgi];
                                c = t.x; codd = t.y;
                            } else {
                                c = codd;
                            }
                            cgi++;
                            ffma2(acc[CUM[l] + m][0], c, p0);
                            ffma2(acc[CUM[l] + m][1], c, p1);
                        }
                    }
                }
            }
        }
    }

#pragma unroll
    for (int l = 0; l < 4; l++) {
        const int dl = 2 * l + 1;
#pragma unroll
        for (int m = 0; m < dl; m++) {
            ulonglong2 v;
            v.x = acc[CUM[l] + m][0]; v.y = acc[CUM[l] + m][1];
            *(ulonglong2*)(oBase + OFFL[l] + (n * dl + m) * KCH + kq) = v;
        }
    }
}

// ============================================================================
// launch
// ============================================================================
extern "C" void kernel_launch(void* const* d_in, const int* in_sizes, int n_in,
                              void* d_out, int out_size)
{
    const float* f[4] = {nullptr, nullptr, nullptr, nullptr};
    const float* mixer = nullptr;
    const float* iterw = nullptr;
    const float* cg = nullptr;

    for (int i = 0; i < n_in; i++) {
        const float* p = (const float*)d_in[i];
        switch (in_sizes[i]) {
            case 2097152:  f[0] = p; break;
            case 6291456:  f[1] = p; break;
            case 10485760: f[2] = p; break;
            case 14680064: f[3] = p; break;
            case 196608:   mixer = p; break;
            case 131072:   iterw = p; break;
            case 21952:    cg = p; break;
        }
    }
    if (!f[0] || !f[1] || !f[2] || !f[3] || !mixer || !iterw || !cg) {
        f[0] = (const float*)d_in[0]; f[1] = (const float*)d_in[1];
        f[2] = (const float*)d_in[2]; f[3] = (const float*)d_in[3];
        mixer = (const float*)d_in[4]; iterw = (const float*)d_in[5];
        cg = (const float*)d_in[6];
    }

    cudaFuncSetAttribute(tc_gemm_stage, cudaFuncAttributeMaxDynamicSharedMemorySize, GEMM_SMEM);

    float* out = (float*)d_out;
    float *m1, *m2, *tpb;
    __nv_bfloat16 *whi, *wlo;
    cudaGetSymbolAddress((void**)&m1, g_m1);
    cudaGetSymbolAddress((void**)&m2, g_m2);
    cudaGetSymbolAddress((void**)&tpb, g_tp);
    cudaGetSymbolAddress((void**)&whi, g_wthi);
    cudaGetSymbolAddress((void**)&wlo, g_wtlo);

    const size_t OFFL[4] = {0, (size_t)1 * NPTS * KCH, (size_t)4 * NPTS * KCH, (size_t)9 * NPTS * KCH};

    prep_cg_kernel<<<(CG_TOTAL + 255) / 256, 256>>>(cg);
    prep_w_kernel<<<NW, 256>>>(mixer, iterw);

    // mixer: mixed[0]->out, mixed[1]->m1, mixed[2]->m2 in ONE launch
    tc_gemm_stage<<<3 * 4096, 256, GEMM_SMEM>>>(
        f[0], f[1], f[2], f[3], out, m1, m2, whi, wlo, /*wbase=*/0, /*accum=*/0);

    // iteration 0: tp = TP(current, mixed1); current += tp @ iter_w[0]
    tp_kernel<<<NPTS * 32 / 256, 256>>>(out, m1, tpb);
    tc_gemm_stage<<<4096, 256, GEMM_SMEM>>>(
        tpb + OFFL[0], tpb + OFFL[1], tpb + OFFL[2], tpb + OFFL[3],
        out, out, out, whi, wlo, /*wbase=*/12, /*accum=*/1);

    // iteration 1: tp = TP(current, mixed2); current += tp @ iter_w[1]
    tp_kernel<<<NPTS * 32 / 256, 256>>>(out, m2, tpb);
    tc_gemm_stage<<<4096, 256, GEMM_SMEM>>>(
        tpb + OFFL[0], tpb + OFFL[1], tpb + OFFL[2], tpb + OFFL[3],
        out, out, out, whi, wlo, /*wbase=*/16, /*accum=*/1);
}